// round 12
// baseline (speedup 1.0000x reference)
#include <cuda_runtime.h>
#include <cuda_fp16.h>
#include <cstdint>

// ---------------------------------------------------------------------------
// Problem constants
constexpr int B_   = 4;
constexpr int G_   = 8;
constexpr int NH_  = 8;
constexpr int DIM_ = 256;    // HID / G
constexpr int S_   = 4096;
constexpr int SPAD = 4104;   // padded K/V time pitch (S_+1, rounded to 8)
constexpr int HID_ = 2048;
constexpr int KP   = 256;    // K (plain fp16, single term)

// ---------------------------------------------------------------------------
// Scratch (device globals; allocation is forbidden) — fp16
__device__ __half g_Q[(size_t)B_ * G_ * DIM_ * S_];    // (bg, c, s)
__device__ __half g_K[(size_t)B_ * G_ * DIM_ * SPAD];  // (bg, c, t) t in [0,4096]
__device__ __half g_V[(size_t)B_ * G_ * DIM_ * SPAD];

__device__ __half g_Bx[(size_t)32 * 256 * S_];
__device__ __half g_Bo[(size_t)32 * 256 * S_];
__device__ __half g_Aq[(size_t)G_ * 768 * KP];  // w_qkv fp16 [g][o][c]
__device__ __half g_Ap[(size_t)G_ * 256 * KP];  // w_pred fp16

// ---------------------------------------------------------------------------
__device__ __forceinline__ uint32_t smem_u32(const void* p) {
    uint32_t a;
    asm("{ .reg .u64 t; cvta.to.shared.u64 t, %1; cvt.u32.u64 %0, t; }" : "=r"(a) : "l"(p));
    return a;
}
__device__ __forceinline__ void cp_async16(uint32_t dst, const void* src) {
    asm volatile("cp.async.cg.shared.global [%0], [%1], 16;" :: "r"(dst), "l"(src));
}
__device__ __forceinline__ void ldmatrix_x4(uint32_t* r, uint32_t addr) {
    asm volatile("ldmatrix.sync.aligned.m8n8.x4.shared.b16 {%0,%1,%2,%3}, [%4];"
                 : "=r"(r[0]), "=r"(r[1]), "=r"(r[2]), "=r"(r[3]) : "r"(addr));
}
__device__ __forceinline__ void ldmatrix_x4_trans(uint32_t* r, uint32_t addr) {
    asm volatile("ldmatrix.sync.aligned.m8n8.x4.trans.shared.b16 {%0,%1,%2,%3}, [%4];"
                 : "=r"(r[0]), "=r"(r[1]), "=r"(r[2]), "=r"(r[3]) : "r"(addr));
}
__device__ __forceinline__ void mma16816(float* c, const uint32_t* a, uint32_t b0, uint32_t b1) {
    asm volatile(
        "mma.sync.aligned.m16n8k16.row.col.f32.f16.f16.f32 "
        "{%0,%1,%2,%3}, {%4,%5,%6,%7}, {%8,%9}, {%0,%1,%2,%3};"
        : "+f"(c[0]), "+f"(c[1]), "+f"(c[2]), "+f"(c[3])
        : "r"(a[0]), "r"(a[1]), "r"(a[2]), "r"(a[3]), "r"(b0), "r"(b1));
}

// ---------------------------------------------------------------------------
// Fused small conversions: w_qkv -> fp16, w_pred -> fp16, K/V pad fill.
// One launch so attention lands at launch index 4 for ncu.
// ---------------------------------------------------------------------------
constexpr int NWQ = G_ * 768 * 256;   // 1572864
constexpr int NWP = G_ * 256 * 256;   // 524288

__global__ void convert_misc(const float* __restrict__ wq,
                             const float* __restrict__ wp,
                             const float* __restrict__ bq,
                             __half* __restrict__ Aq, __half* __restrict__ Ap) {
    int i = blockIdx.x * 256 + threadIdx.x;
    if (i < NWQ) { Aq[i] = __float2half(wq[i]); return; }
    i -= NWQ;
    if (i < NWP) { Ap[i] = __float2half(wp[i]); return; }
    i -= NWP;
    if (i < 32 * 256) {
        int bg = i >> 8, c2 = i & 255, g = bg & 7;
        g_K[((size_t)bg * DIM_ + c2) * SPAD + S_] = __float2half(bq[g * 768 + c2 * 3 + 1]);
        g_V[((size_t)bg * DIM_ + c2) * SPAD + S_] = __float2half(bq[g * 768 + c2 * 3 + 2]);
    }
}

// x fp32 -> g_Bx fp16 (elementwise)
__global__ __launch_bounds__(256)
void convert_x(const float* __restrict__ x, __half* __restrict__ dst) {
    int i = blockIdx.x * 256 + threadIdx.x;  // over 32*256*1024 float4 slots
    size_t base = (size_t)i << 2;
    float4 v = *reinterpret_cast<const float4*>(x + base);
    __half2 h0, h1;
    h0.x = __float2half(v.x); h0.y = __float2half(v.y);
    h1.x = __float2half(v.z); h1.y = __float2half(v.w);
    __half2* dh = reinterpret_cast<__half2*>(dst + base);
    dh[0] = h0; dh[1] = h1;
}

// ---------------------------------------------------------------------------
// mma.sync GEMM: unchanged from round 9 (known good).
// ---------------------------------------------------------------------------
constexpr int NCH = 8;

__global__ __launch_bounds__(128, 2)
void gemm_mma(const __half* __restrict__ Aall,
              const __half* __restrict__ Ball,
              const float* __restrict__ bias,
              int Mtot, int mode, float* __restrict__ out) {
    extern __shared__ __align__(1024) char sbuf[];  // 4 * 16384
    const int tid  = threadIdx.x;
    const int lane = tid & 31;
    const int wid  = tid >> 5;
    const int wm   = wid & 1;
    const int wn   = wid >> 1;
    const int bg = blockIdx.z, g = bg & 7;
    const int o0 = blockIdx.y * 128, t0 = blockIdx.x * 128;

    const uint32_t sbase = smem_u32(sbuf);
    const __half* A  = Aall + ((size_t)g * Mtot + o0) * KP;
    const __half* Bp = Ball + (size_t)bg * 256 * S_;

    auto load_stage = [&](int ch, int st) {
        uint32_t sA = sbase + st * 16384;
        uint32_t sB = sA + 8192;
        const char* a8 = (const char*)A + (size_t)ch * 64;
        const char* b8 = (const char*)(Bp + ((size_t)ch * 32) * S_ + t0);
#pragma unroll
        for (int i = 0; i < 4; i++) {
            int id = tid + i * 128;
            int ra = id >> 2, ca = id & 3;
            uint32_t offA = ra * 64 + ((ca ^ ((ra >> 1) & 3)) << 4);
            cp_async16(sA + offA, a8 + (size_t)ra * (KP * 2) + ca * 16);
            int rb = id >> 4, cb = id & 15;
            uint32_t offB = rb * 256 + ((cb ^ (rb & 7)) << 4);
            cp_async16(sB + offB, b8 + (size_t)rb * (S_ * 2) + cb * 16);
        }
    };

    float acc[4][8][4];
#pragma unroll
    for (int mi = 0; mi < 4; mi++)
#pragma unroll
        for (int nj = 0; nj < 8; nj++)
#pragma unroll
            for (int q = 0; q < 4; q++) acc[mi][nj][q] = 0.f;

    load_stage(0, 0);
    asm volatile("cp.async.commit_group;" ::: "memory");
    load_stage(1, 1);
    asm volatile("cp.async.commit_group;" ::: "memory");
    load_stage(2, 2);
    asm volatile("cp.async.commit_group;" ::: "memory");

    const int gsel = lane >> 3;
    const int rin  = lane & 7;
    const int bl   = lane & 15;
    const int bh   = lane >> 4;

    for (int ch = 0; ch < NCH; ch++) {
        if (ch < NCH - 3) asm volatile("cp.async.wait_group 2;" ::: "memory");
        else              asm volatile("cp.async.wait_group 0;" ::: "memory");
        __syncthreads();
        if (ch + 3 < NCH) {
            load_stage(ch + 3, (ch + 3) & 3);
            asm volatile("cp.async.commit_group;" ::: "memory");
        }
        uint32_t sA = sbase + (ch & 3) * 16384;
        uint32_t sB = sA + 8192;
#pragma unroll
        for (int kk = 0; kk < 2; kk++) {
            uint32_t afr[4][4];
#pragma unroll
            for (int mi = 0; mi < 4; mi++) {
                int row   = wm * 64 + mi * 16 + (gsel & 1) * 8 + rin;
                int chunk = kk * 2 + (gsel >> 1);
                uint32_t addr = sA + row * 64 + ((chunk ^ ((row >> 1) & 3)) << 4);
                ldmatrix_x4(afr[mi], addr);
            }
            uint32_t bfr[4][4];
#pragma unroll
            for (int nt = 0; nt < 4; nt++) {
                int krow  = kk * 16 + bl;
                int chunk = wn * 8 + nt * 2 + bh;
                uint32_t addr = sB + krow * 256 + ((chunk ^ (krow & 7)) << 4);
                ldmatrix_x4_trans(bfr[nt], addr);
            }
#pragma unroll
            for (int mi = 0; mi < 4; mi++)
#pragma unroll
                for (int nj = 0; nj < 8; nj++)
                    mma16816(acc[mi][nj], afr[mi],
                             bfr[nj >> 1][(nj & 1) * 2], bfr[nj >> 1][(nj & 1) * 2 + 1]);
        }
    }

    // Epilogue
#pragma unroll
    for (int mi = 0; mi < 4; mi++) {
#pragma unroll
        for (int half = 0; half < 2; half++) {
            int o = o0 + wm * 64 + mi * 16 + half * 8 + (lane >> 2);
            if (mode == 0) {
                int c2 = o / 3;
                int j  = o - c2 * 3;
                float bv = bias[g * 768 + o];
                __half* dst;
                if (j == 0)      dst = g_Q + ((size_t)bg * DIM_ + c2) * S_;
                else if (j == 1) dst = g_K + ((size_t)bg * DIM_ + c2) * SPAD;
                else             dst = g_V + ((size_t)bg * DIM_ + c2) * SPAD;
                dst += t0 + wn * 64 + (lane & 3) * 2;
#pragma unroll
                for (int nj = 0; nj < 8; nj++) {
                    __half2 hv;
                    hv.x = __float2half(acc[mi][nj][half * 2 + 0] + bv);
                    hv.y = __float2half(acc[mi][nj][half * 2 + 1] + bv);
                    *reinterpret_cast<__half2*>(dst + nj * 8) = hv;
                }
            } else {
                float bv = bias[g * 256 + o];
                float* dst = out + ((size_t)bg * 256 + o) * S_
                           + t0 + wn * 64 + (lane & 3) * 2;
#pragma unroll
                for (int nj = 0; nj < 8; nj++) {
                    float2 v;
                    v.x = acc[mi][nj][half * 2 + 0] + bv;
                    v.y = acc[mi][nj][half * 2 + 1] + bv;
                    *reinterpret_cast<float2*>(dst + nj * 8) = v;
                }
            }
        }
    }
}

// ---------------------------------------------------------------------------
// Attention: one thread per (b, n, s); K and V staged through smem tiles.
// Tile = 128 rows (8e x 16d) x 136 t-columns fp16 (34 KB). Both the aligned
// [tid] and shifted [tid+1] reads come from the same smem row.
// FMA order identical to round 9 -> bitwise-identical results.
// ---------------------------------------------------------------------------
__global__ __launch_bounds__(128)
void attn_kernel(float* __restrict__ attn_out) {
    __shared__ __half sT[128][136];
    const int tid = threadIdx.x;
    const int s0  = blockIdx.x * 128;
    const int s   = s0 + tid;
    const int n   = blockIdx.y;
    const int b   = blockIdx.z;

    const __half* Kb = g_K + (size_t)b * G_ * DIM_ * SPAD;
    const __half* Vb = g_V + (size_t)b * G_ * DIM_ * SPAD;
    const size_t qbase = ((size_t)b * G_ * DIM_ + n * 32) * S_ + s;

    float sc[8][16];
#pragma unroll
    for (int g = 0; g < 8; g++)
#pragma unroll
        for (int e = 0; e < 16; e++) sc[g][e] = 0.f;

    // ---- scores: two d-chunks of 16, K tile staged in smem ----
    for (int hf = 0; hf < 2; hf++) {
        const int d0 = hf * 16;
        __syncthreads();  // protect previous tile contents
        for (int j = tid; j < 128 * 17; j += 128) {
            int r = j / 17, c = j - r * 17;
            int e = r >> 4, dl = r & 15;
            const uint4* p = reinterpret_cast<const uint4*>(
                Kb + (size_t)(e * DIM_ + n * 32 + d0 + dl) * SPAD + s0) + c;
            *reinterpret_cast<uint4*>(&sT[r][c * 8]) = *p;
        }
        __syncthreads();
#pragma unroll
        for (int dl = 0; dl < 16; dl++) {
            float qv[8], kv[16];
#pragma unroll
            for (int g = 0; g < 8; g++)
                qv[g] = __half2float(g_Q[qbase + (size_t)(g * DIM_ + d0 + dl) * S_]);
#pragma unroll
            for (int e = 0; e < 8; e++) {
                kv[e]     = __half2float(sT[e * 16 + dl][tid]);
                kv[e + 8] = __half2float(sT[e * 16 + dl][tid + 1]);
            }
#pragma unroll
            for (int g = 0; g < 8; g++)
#pragma unroll
                for (int e = 0; e < 16; e++) sc[g][e] += qv[g] * kv[e];
        }
    }

    // ---- sigmoid + normalization + attn_out ----
    const float scale = 0.17677669529663687f;  // 1/sqrt(32)
    const size_t abase = (size_t)(b * NH_ + n) * 128 * S_ + s;
#pragma unroll
    for (int g = 0; g < 8; g++) {
        float rs = 1e-9f;
#pragma unroll
        for (int e = 0; e < 16; e++) {
            float z = 1.f / (1.f + __expf(-sc[g][e] * scale));
            sc[g][e] = z;
            rs += z;
        }
        float inv = 1.f / rs;
#pragma unroll
        for (int e = 0; e < 16; e++) {
            sc[g][e] *= inv;
            attn_out[abase + (size_t)(g * 16 + e) * S_] = sc[g][e];
        }
    }

    // ---- AV: two d-chunks, V tile staged in smem; write fp16 into g_Bo ----
    for (int hf = 0; hf < 2; hf++) {
        const int d0 = hf * 16;
        __syncthreads();
        for (int j = tid; j < 128 * 17; j += 128) {
            int r = j / 17, c = j - r * 17;
            int e = r >> 4, dl = r & 15;
            const uint4* p = reinterpret_cast<const uint4*>(
                Vb + (size_t)(e * DIM_ + n * 32 + d0 + dl) * SPAD + s0) + c;
            *reinterpret_cast<uint4*>(&sT[r][c * 8]) = *p;
        }
        __syncthreads();
#pragma unroll
        for (int dl = 0; dl < 16; dl++) {
            float vv[16];
#pragma unroll
            for (int e = 0; e < 8; e++) {
                vv[e]     = __half2float(sT[e * 16 + dl][tid]);
                vv[e + 8] = __half2float(sT[e * 16 + dl][tid + 1]);
            }
#pragma unroll
            for (int g = 0; g < 8; g++) {
                float a = 0.f;
#pragma unroll
                for (int e = 0; e < 16; e++) a += sc[g][e] * vv[e];
                g_Bo[((size_t)(b * 8 + g) * 256 + n * 32 + d0 + dl) * S_ + s] =
                    __float2half(a);
            }
        }
    }
}

// ---------------------------------------------------------------------------
// Serial launcher. Launch order puts attn_kernel 4th for ncu capture.
// ---------------------------------------------------------------------------
extern "C" void kernel_launch(void* const* d_in, const int* in_sizes, int n_in,
                              void* d_out, int out_size) {
    const float* x      = (const float*)d_in[0];
    const float* w_qkv  = (const float*)d_in[1];
    const float* b_qkv  = (const float*)d_in[2];
    const float* w_pred = (const float*)d_in[3];
    const float* b_pred = (const float*)d_in[4];

    float* pred = (float*)d_out;
    float* attn = pred + (size_t)B_ * HID_ * S_;

    void *pAq, *pAp, *pBx, *pBo;
    cudaGetSymbolAddress(&pAq, g_Aq);
    cudaGetSymbolAddress(&pAp, g_Ap);
    cudaGetSymbolAddress(&pBx, g_Bx);
    cudaGetSymbolAddress(&pBo, g_Bo);

    cudaFuncSetAttribute(gemm_mma, cudaFuncAttributeMaxDynamicSharedMemorySize, 65536);

    convert_misc<<<(NWQ + NWP + 32 * 256 + 255) / 256, 256>>>(
        w_qkv, w_pred, b_qkv, (__half*)pAq, (__half*)pAp);

    convert_x<<<32 * 256 * 1024 / 256, 256>>>(x, (__half*)pBx);

    gemm_mma<<<dim3(32, 6, 32), 128, 65536>>>((const __half*)pAq,
                                              (const __half*)pBx,
                                              b_qkv, 768, 0, nullptr);

    attn_kernel<<<dim3(S_ / 128, NH_, B_), 128>>>(attn);

    gemm_mma<<<dim3(32, 2, 32), 128, 65536>>>((const __half*)pAp,
                                              (const __half*)pBo,
                                              b_pred, 256, 1, pred);
}

// round 13
// speedup vs baseline: 1.1629x; 1.1629x over previous
#include <cuda_runtime.h>
#include <cuda_fp16.h>
#include <cstdint>

// ---------------------------------------------------------------------------
// Problem constants
constexpr int B_   = 4;
constexpr int G_   = 8;
constexpr int NH_  = 8;
constexpr int DIM_ = 256;    // HID / G
constexpr int S_   = 4096;
constexpr int SPAD = 4104;   // padded K/V time pitch (S_+1, rounded to 8)
constexpr int HID_ = 2048;
constexpr int KP   = 256;    // K (plain fp16, single term)

// ---------------------------------------------------------------------------
// Scratch (device globals; allocation is forbidden) — fp16
__device__ __half g_Q[(size_t)B_ * G_ * DIM_ * S_];    // (bg, c, s)
__device__ __half g_K[(size_t)B_ * G_ * DIM_ * SPAD];  // (bg, c, t) t in [0,4096]
__device__ __half g_V[(size_t)B_ * G_ * DIM_ * SPAD];

__device__ __half g_Bx[(size_t)32 * 256 * S_];
__device__ __half g_Bo[(size_t)32 * 256 * S_];
__device__ __half g_Aq[(size_t)G_ * 768 * KP];  // w_qkv fp16 [g][o][c]
__device__ __half g_Ap[(size_t)G_ * 256 * KP];  // w_pred fp16

// ---------------------------------------------------------------------------
__device__ __forceinline__ uint32_t smem_u32(const void* p) {
    uint32_t a;
    asm("{ .reg .u64 t; cvta.to.shared.u64 t, %1; cvt.u32.u64 %0, t; }" : "=r"(a) : "l"(p));
    return a;
}
__device__ __forceinline__ void cp_async16(uint32_t dst, const void* src) {
    asm volatile("cp.async.cg.shared.global [%0], [%1], 16;" :: "r"(dst), "l"(src));
}
__device__ __forceinline__ void ldmatrix_x4(uint32_t* r, uint32_t addr) {
    asm volatile("ldmatrix.sync.aligned.m8n8.x4.shared.b16 {%0,%1,%2,%3}, [%4];"
                 : "=r"(r[0]), "=r"(r[1]), "=r"(r[2]), "=r"(r[3]) : "r"(addr));
}
__device__ __forceinline__ void ldmatrix_x4_trans(uint32_t* r, uint32_t addr) {
    asm volatile("ldmatrix.sync.aligned.m8n8.x4.trans.shared.b16 {%0,%1,%2,%3}, [%4];"
                 : "=r"(r[0]), "=r"(r[1]), "=r"(r[2]), "=r"(r[3]) : "r"(addr));
}
__device__ __forceinline__ void mma16816(float* c, const uint32_t* a, uint32_t b0, uint32_t b1) {
    asm volatile(
        "mma.sync.aligned.m16n8k16.row.col.f32.f16.f16.f32 "
        "{%0,%1,%2,%3}, {%4,%5,%6,%7}, {%8,%9}, {%0,%1,%2,%3};"
        : "+f"(c[0]), "+f"(c[1]), "+f"(c[2]), "+f"(c[3])
        : "r"(a[0]), "r"(a[1]), "r"(a[2]), "r"(a[3]), "r"(b0), "r"(b1));
}

// ---------------------------------------------------------------------------
// Fused small conversions: w_qkv -> fp16, w_pred -> fp16, K/V pad fill.
// ---------------------------------------------------------------------------
constexpr int NWQ = G_ * 768 * 256;   // 1572864
constexpr int NWP = G_ * 256 * 256;   // 524288

__global__ void convert_misc(const float* __restrict__ wq,
                             const float* __restrict__ wp,
                             const float* __restrict__ bq,
                             __half* __restrict__ Aq, __half* __restrict__ Ap) {
    int i = blockIdx.x * 256 + threadIdx.x;
    if (i < NWQ) { Aq[i] = __float2half(wq[i]); return; }
    i -= NWQ;
    if (i < NWP) { Ap[i] = __float2half(wp[i]); return; }
    i -= NWP;
    if (i < 32 * 256) {
        int bg = i >> 8, c2 = i & 255, g = bg & 7;
        g_K[((size_t)bg * DIM_ + c2) * SPAD + S_] = __float2half(bq[g * 768 + c2 * 3 + 1]);
        g_V[((size_t)bg * DIM_ + c2) * SPAD + S_] = __float2half(bq[g * 768 + c2 * 3 + 2]);
    }
}

// x fp32 -> g_Bx fp16 (elementwise)
__global__ __launch_bounds__(256)
void convert_x(const float* __restrict__ x, __half* __restrict__ dst) {
    int i = blockIdx.x * 256 + threadIdx.x;  // over 32*256*1024 float4 slots
    size_t base = (size_t)i << 2;
    float4 v = *reinterpret_cast<const float4*>(x + base);
    __half2 h0, h1;
    h0.x = __float2half(v.x); h0.y = __float2half(v.y);
    h1.x = __float2half(v.z); h1.y = __float2half(v.w);
    __half2* dh = reinterpret_cast<__half2*>(dst + base);
    dh[0] = h0; dh[1] = h1;
}

// ---------------------------------------------------------------------------
// mma.sync GEMM: unchanged from round 9 (known good).
// ---------------------------------------------------------------------------
constexpr int NCH = 8;

__global__ __launch_bounds__(128, 2)
void gemm_mma(const __half* __restrict__ Aall,
              const __half* __restrict__ Ball,
              const float* __restrict__ bias,
              int Mtot, int mode, float* __restrict__ out) {
    extern __shared__ __align__(1024) char sbuf[];  // 4 * 16384
    const int tid  = threadIdx.x;
    const int lane = tid & 31;
    const int wid  = tid >> 5;
    const int wm   = wid & 1;
    const int wn   = wid >> 1;
    const int bg = blockIdx.z, g = bg & 7;
    const int o0 = blockIdx.y * 128, t0 = blockIdx.x * 128;

    const uint32_t sbase = smem_u32(sbuf);
    const __half* A  = Aall + ((size_t)g * Mtot + o0) * KP;
    const __half* Bp = Ball + (size_t)bg * 256 * S_;

    auto load_stage = [&](int ch, int st) {
        uint32_t sA = sbase + st * 16384;
        uint32_t sB = sA + 8192;
        const char* a8 = (const char*)A + (size_t)ch * 64;
        const char* b8 = (const char*)(Bp + ((size_t)ch * 32) * S_ + t0);
#pragma unroll
        for (int i = 0; i < 4; i++) {
            int id = tid + i * 128;
            int ra = id >> 2, ca = id & 3;
            uint32_t offA = ra * 64 + ((ca ^ ((ra >> 1) & 3)) << 4);
            cp_async16(sA + offA, a8 + (size_t)ra * (KP * 2) + ca * 16);
            int rb = id >> 4, cb = id & 15;
            uint32_t offB = rb * 256 + ((cb ^ (rb & 7)) << 4);
            cp_async16(sB + offB, b8 + (size_t)rb * (S_ * 2) + cb * 16);
        }
    };

    float acc[4][8][4];
#pragma unroll
    for (int mi = 0; mi < 4; mi++)
#pragma unroll
        for (int nj = 0; nj < 8; nj++)
#pragma unroll
            for (int q = 0; q < 4; q++) acc[mi][nj][q] = 0.f;

    load_stage(0, 0);
    asm volatile("cp.async.commit_group;" ::: "memory");
    load_stage(1, 1);
    asm volatile("cp.async.commit_group;" ::: "memory");
    load_stage(2, 2);
    asm volatile("cp.async.commit_group;" ::: "memory");

    const int gsel = lane >> 3;
    const int rin  = lane & 7;
    const int bl   = lane & 15;
    const int bh   = lane >> 4;

    for (int ch = 0; ch < NCH; ch++) {
        if (ch < NCH - 3) asm volatile("cp.async.wait_group 2;" ::: "memory");
        else              asm volatile("cp.async.wait_group 0;" ::: "memory");
        __syncthreads();
        if (ch + 3 < NCH) {
            load_stage(ch + 3, (ch + 3) & 3);
            asm volatile("cp.async.commit_group;" ::: "memory");
        }
        uint32_t sA = sbase + (ch & 3) * 16384;
        uint32_t sB = sA + 8192;
#pragma unroll
        for (int kk = 0; kk < 2; kk++) {
            uint32_t afr[4][4];
#pragma unroll
            for (int mi = 0; mi < 4; mi++) {
                int row   = wm * 64 + mi * 16 + (gsel & 1) * 8 + rin;
                int chunk = kk * 2 + (gsel >> 1);
                uint32_t addr = sA + row * 64 + ((chunk ^ ((row >> 1) & 3)) << 4);
                ldmatrix_x4(afr[mi], addr);
            }
            uint32_t bfr[4][4];
#pragma unroll
            for (int nt = 0; nt < 4; nt++) {
                int krow  = kk * 16 + bl;
                int chunk = wn * 8 + nt * 2 + bh;
                uint32_t addr = sB + krow * 256 + ((chunk ^ (krow & 7)) << 4);
                ldmatrix_x4_trans(bfr[nt], addr);
            }
#pragma unroll
            for (int mi = 0; mi < 4; mi++)
#pragma unroll
                for (int nj = 0; nj < 8; nj++)
                    mma16816(acc[mi][nj], afr[mi],
                             bfr[nj >> 1][(nj & 1) * 2], bfr[nj >> 1][(nj & 1) * 2 + 1]);
        }
    }

    // Epilogue
#pragma unroll
    for (int mi = 0; mi < 4; mi++) {
#pragma unroll
        for (int half = 0; half < 2; half++) {
            int o = o0 + wm * 64 + mi * 16 + half * 8 + (lane >> 2);
            if (mode == 0) {
                int c2 = o / 3;
                int j  = o - c2 * 3;
                float bv = bias[g * 768 + o];
                __half* dst;
                if (j == 0)      dst = g_Q + ((size_t)bg * DIM_ + c2) * S_;
                else if (j == 1) dst = g_K + ((size_t)bg * DIM_ + c2) * SPAD;
                else             dst = g_V + ((size_t)bg * DIM_ + c2) * SPAD;
                dst += t0 + wn * 64 + (lane & 3) * 2;
#pragma unroll
                for (int nj = 0; nj < 8; nj++) {
                    __half2 hv;
                    hv.x = __float2half(acc[mi][nj][half * 2 + 0] + bv);
                    hv.y = __float2half(acc[mi][nj][half * 2 + 1] + bv);
                    *reinterpret_cast<__half2*>(dst + nj * 8) = hv;
                }
            } else {
                float bv = bias[g * 256 + o];
                float* dst = out + ((size_t)bg * 256 + o) * S_
                           + t0 + wn * 64 + (lane & 3) * 2;
#pragma unroll
                for (int nj = 0; nj < 8; nj++) {
                    float2 v;
                    v.x = acc[mi][nj][half * 2 + 0] + bv;
                    v.y = acc[mi][nj][half * 2 + 1] + bv;
                    *reinterpret_cast<float2*>(dst + nj * 8) = v;
                }
            }
        }
    }
}

// ---------------------------------------------------------------------------
// Attention: block (128 s-lanes, 4 g-pairs) = 512 threads.
// ty owns g in {2ty, 2ty+1}: sc[2][16] accumulators (32 regs) -> low pressure,
// 16 warps/SM. K/V staged ONCE per block in smem (no redundant DRAM traffic).
// Accumulation order over d identical to rounds 9/12 -> same numerics.
// ---------------------------------------------------------------------------
__global__ __launch_bounds__(512, 1)
void attn_kernel(float* __restrict__ attn_out) {
    __shared__ __half sT[128][136];  // 34 KB tile: rows = e*16+dl, cols = t
    const int tx  = threadIdx.x;     // s lane
    const int ty  = threadIdx.y;     // g pair
    const int tid = ty * 128 + tx;
    const int g0  = ty * 2;
    const int s0  = blockIdx.x * 128;
    const int s   = s0 + tx;
    const int n   = blockIdx.y;
    const int b   = blockIdx.z;

    const __half* Kb = g_K + (size_t)b * G_ * DIM_ * SPAD;
    const __half* Vb = g_V + (size_t)b * G_ * DIM_ * SPAD;
    const size_t qbase = ((size_t)b * G_ * DIM_ + g0 * DIM_ + n * 32) * S_ + s;

    float sc[2][16];
#pragma unroll
    for (int gi = 0; gi < 2; gi++)
#pragma unroll
        for (int e = 0; e < 16; e++) sc[gi][e] = 0.f;

    // ---- scores: two d-chunks of 16, K tile staged in smem ----
    for (int hf = 0; hf < 2; hf++) {
        const int d0 = hf * 16;
        __syncthreads();
        for (int j = tid; j < 128 * 17; j += 512) {
            int r = j / 17, c = j - r * 17;
            int e = r >> 4, dl = r & 15;
            const uint4* p = reinterpret_cast<const uint4*>(
                Kb + (size_t)(e * DIM_ + n * 32 + d0 + dl) * SPAD + s0) + c;
            *reinterpret_cast<uint4*>(&sT[r][c * 8]) = *p;
        }
        __syncthreads();
#pragma unroll
        for (int dl = 0; dl < 16; dl++) {
            float qv[2], kv[16];
            qv[0] = __half2float(g_Q[qbase + (size_t)(d0 + dl) * S_]);
            qv[1] = __half2float(g_Q[qbase + (size_t)(DIM_ + d0 + dl) * S_]);
#pragma unroll
            for (int e = 0; e < 8; e++) {
                kv[e]     = __half2float(sT[e * 16 + dl][tx]);
                kv[e + 8] = __half2float(sT[e * 16 + dl][tx + 1]);
            }
#pragma unroll
            for (int gi = 0; gi < 2; gi++)
#pragma unroll
                for (int e = 0; e < 16; e++) sc[gi][e] += qv[gi] * kv[e];
        }
    }

    // ---- sigmoid + normalization + attn_out ----
    const float scale = 0.17677669529663687f;  // 1/sqrt(32)
    const size_t abase = (size_t)(b * NH_ + n) * 128 * S_ + s;
#pragma unroll
    for (int gi = 0; gi < 2; gi++) {
        float rs = 1e-9f;
#pragma unroll
        for (int e = 0; e < 16; e++) {
            float z = 1.f / (1.f + __expf(-sc[gi][e] * scale));
            sc[gi][e] = z;
            rs += z;
        }
        float inv = 1.f / rs;
#pragma unroll
        for (int e = 0; e < 16; e++) {
            sc[gi][e] *= inv;
            attn_out[abase + (size_t)((g0 + gi) * 16 + e) * S_] = sc[gi][e];
        }
    }

    // ---- AV: two d-chunks, V tile staged in smem; fp16 into g_Bo ----
    for (int hf = 0; hf < 2; hf++) {
        const int d0 = hf * 16;
        __syncthreads();
        for (int j = tid; j < 128 * 17; j += 512) {
            int r = j / 17, c = j - r * 17;
            int e = r >> 4, dl = r & 15;
            const uint4* p = reinterpret_cast<const uint4*>(
                Vb + (size_t)(e * DIM_ + n * 32 + d0 + dl) * SPAD + s0) + c;
            *reinterpret_cast<uint4*>(&sT[r][c * 8]) = *p;
        }
        __syncthreads();
#pragma unroll
        for (int dl = 0; dl < 16; dl++) {
            float vv[16];
#pragma unroll
            for (int e = 0; e < 8; e++) {
                vv[e]     = __half2float(sT[e * 16 + dl][tx]);
                vv[e + 8] = __half2float(sT[e * 16 + dl][tx + 1]);
            }
#pragma unroll
            for (int gi = 0; gi < 2; gi++) {
                float a = 0.f;
#pragma unroll
                for (int e = 0; e < 16; e++) a += sc[gi][e] * vv[e];
                g_Bo[((size_t)(b * 8 + g0 + gi) * 256 + n * 32 + d0 + dl) * S_ + s] =
                    __float2half(a);
            }
        }
    }
}

// ---------------------------------------------------------------------------
// Serial launcher; attn_kernel is launch #4 for ncu capture.
// ---------------------------------------------------------------------------
extern "C" void kernel_launch(void* const* d_in, const int* in_sizes, int n_in,
                              void* d_out, int out_size) {
    const float* x      = (const float*)d_in[0];
    const float* w_qkv  = (const float*)d_in[1];
    const float* b_qkv  = (const float*)d_in[2];
    const float* w_pred = (const float*)d_in[3];
    const float* b_pred = (const float*)d_in[4];

    float* pred = (float*)d_out;
    float* attn = pred + (size_t)B_ * HID_ * S_;

    void *pAq, *pAp, *pBx, *pBo;
    cudaGetSymbolAddress(&pAq, g_Aq);
    cudaGetSymbolAddress(&pAp, g_Ap);
    cudaGetSymbolAddress(&pBx, g_Bx);
    cudaGetSymbolAddress(&pBo, g_Bo);

    cudaFuncSetAttribute(gemm_mma, cudaFuncAttributeMaxDynamicSharedMemorySize, 65536);

    convert_misc<<<(NWQ + NWP + 32 * 256 + 255) / 256, 256>>>(
        w_qkv, w_pred, b_qkv, (__half*)pAq, (__half*)pAp);

    convert_x<<<32 * 256 * 1024 / 256, 256>>>(x, (__half*)pBx);

    gemm_mma<<<dim3(32, 6, 32), 128, 65536>>>((const __half*)pAq,
                                              (const __half*)pBx,
                                              b_qkv, 768, 0, nullptr);

    attn_kernel<<<dim3(S_ / 128, NH_, B_), dim3(128, 4)>>>(attn);

    gemm_mma<<<dim3(32, 2, 32), 128, 65536>>>((const __half*)pAp,
                                              (const __half*)pBo,
                                              b_pred, 256, 1, pred);
}

// round 14
// speedup vs baseline: 1.4002x; 1.2040x over previous
#include <cuda_runtime.h>
#include <cuda_fp16.h>
#include <cstdint>

// ---------------------------------------------------------------------------
// Problem constants
constexpr int B_   = 4;
constexpr int G_   = 8;
constexpr int NH_  = 8;
constexpr int DIM_ = 256;    // HID / G
constexpr int S_   = 4096;
constexpr int SPAD = 4104;   // padded K/V time pitch (S_+1, rounded to 8)
constexpr int HID_ = 2048;
constexpr int KP   = 256;    // K (plain fp16, single term)

// ---------------------------------------------------------------------------
// Scratch (device globals; allocation is forbidden) — fp16
__device__ __half g_Q[(size_t)B_ * G_ * DIM_ * S_];    // (bg, c, s)
__device__ __half g_K[(size_t)B_ * G_ * DIM_ * SPAD];  // (bg, c, t) t in [0,4096]
__device__ __half g_V[(size_t)B_ * G_ * DIM_ * SPAD];

__device__ __half g_Bx[(size_t)32 * 256 * S_];
__device__ __half g_Bo[(size_t)32 * 256 * S_];
__device__ __half g_Aq[(size_t)G_ * 768 * KP];  // w_qkv fp16 [g][o][c]
__device__ __half g_Ap[(size_t)G_ * 256 * KP];  // w_pred fp16

// ---------------------------------------------------------------------------
__device__ __forceinline__ uint32_t smem_u32(const void* p) {
    uint32_t a;
    asm("{ .reg .u64 t; cvta.to.shared.u64 t, %1; cvt.u32.u64 %0, t; }" : "=r"(a) : "l"(p));
    return a;
}
__device__ __forceinline__ void cp_async16(uint32_t dst, const void* src) {
    asm volatile("cp.async.cg.shared.global [%0], [%1], 16;" :: "r"(dst), "l"(src));
}
__device__ __forceinline__ void ldmatrix_x4(uint32_t* r, uint32_t addr) {
    asm volatile("ldmatrix.sync.aligned.m8n8.x4.shared.b16 {%0,%1,%2,%3}, [%4];"
                 : "=r"(r[0]), "=r"(r[1]), "=r"(r[2]), "=r"(r[3]) : "r"(addr));
}
__device__ __forceinline__ void ldmatrix_x4_trans(uint32_t* r, uint32_t addr) {
    asm volatile("ldmatrix.sync.aligned.m8n8.x4.trans.shared.b16 {%0,%1,%2,%3}, [%4];"
                 : "=r"(r[0]), "=r"(r[1]), "=r"(r[2]), "=r"(r[3]) : "r"(addr));
}
__device__ __forceinline__ void mma16816(float* c, const uint32_t* a, uint32_t b0, uint32_t b1) {
    asm volatile(
        "mma.sync.aligned.m16n8k16.row.col.f32.f16.f16.f32 "
        "{%0,%1,%2,%3}, {%4,%5,%6,%7}, {%8,%9}, {%0,%1,%2,%3};"
        : "+f"(c[0]), "+f"(c[1]), "+f"(c[2]), "+f"(c[3])
        : "r"(a[0]), "r"(a[1]), "r"(a[2]), "r"(a[3]), "r"(b0), "r"(b1));
}

// ---------------------------------------------------------------------------
// Fused small conversions: w_qkv -> fp16, w_pred -> fp16, K/V pad fill.
// ---------------------------------------------------------------------------
constexpr int NWQ = G_ * 768 * 256;   // 1572864
constexpr int NWP = G_ * 256 * 256;   // 524288

__global__ void convert_misc(const float* __restrict__ wq,
                             const float* __restrict__ wp,
                             const float* __restrict__ bq,
                             __half* __restrict__ Aq, __half* __restrict__ Ap) {
    int i = blockIdx.x * 256 + threadIdx.x;
    if (i < NWQ) { Aq[i] = __float2half(wq[i]); return; }
    i -= NWQ;
    if (i < NWP) { Ap[i] = __float2half(wp[i]); return; }
    i -= NWP;
    if (i < 32 * 256) {
        int bg = i >> 8, c2 = i & 255, g = bg & 7;
        g_K[((size_t)bg * DIM_ + c2) * SPAD + S_] = __float2half(bq[g * 768 + c2 * 3 + 1]);
        g_V[((size_t)bg * DIM_ + c2) * SPAD + S_] = __float2half(bq[g * 768 + c2 * 3 + 2]);
    }
}

// x fp32 -> g_Bx fp16 (elementwise)
__global__ __launch_bounds__(256)
void convert_x(const float* __restrict__ x, __half* __restrict__ dst) {
    int i = blockIdx.x * 256 + threadIdx.x;  // over 32*256*1024 float4 slots
    size_t base = (size_t)i << 2;
    float4 v = *reinterpret_cast<const float4*>(x + base);
    __half2 h0, h1;
    h0.x = __float2half(v.x); h0.y = __float2half(v.y);
    h1.x = __float2half(v.z); h1.y = __float2half(v.w);
    __half2* dh = reinterpret_cast<__half2*>(dst + base);
    dh[0] = h0; dh[1] = h1;
}

// ---------------------------------------------------------------------------
// mma.sync GEMM: unchanged from round 9 (known good).
// ---------------------------------------------------------------------------
constexpr int NCH = 8;

__global__ __launch_bounds__(128, 2)
void gemm_mma(const __half* __restrict__ Aall,
              const __half* __restrict__ Ball,
              const float* __restrict__ bias,
              int Mtot, int mode, float* __restrict__ out) {
    extern __shared__ __align__(1024) char sbuf[];  // 4 * 16384
    const int tid  = threadIdx.x;
    const int lane = tid & 31;
    const int wid  = tid >> 5;
    const int wm   = wid & 1;
    const int wn   = wid >> 1;
    const int bg = blockIdx.z, g = bg & 7;
    const int o0 = blockIdx.y * 128, t0 = blockIdx.x * 128;

    const uint32_t sbase = smem_u32(sbuf);
    const __half* A  = Aall + ((size_t)g * Mtot + o0) * KP;
    const __half* Bp = Ball + (size_t)bg * 256 * S_;

    auto load_stage = [&](int ch, int st) {
        uint32_t sA = sbase + st * 16384;
        uint32_t sB = sA + 8192;
        const char* a8 = (const char*)A + (size_t)ch * 64;
        const char* b8 = (const char*)(Bp + ((size_t)ch * 32) * S_ + t0);
#pragma unroll
        for (int i = 0; i < 4; i++) {
            int id = tid + i * 128;
            int ra = id >> 2, ca = id & 3;
            uint32_t offA = ra * 64 + ((ca ^ ((ra >> 1) & 3)) << 4);
            cp_async16(sA + offA, a8 + (size_t)ra * (KP * 2) + ca * 16);
            int rb = id >> 4, cb = id & 15;
            uint32_t offB = rb * 256 + ((cb ^ (rb & 7)) << 4);
            cp_async16(sB + offB, b8 + (size_t)rb * (S_ * 2) + cb * 16);
        }
    };

    float acc[4][8][4];
#pragma unroll
    for (int mi = 0; mi < 4; mi++)
#pragma unroll
        for (int nj = 0; nj < 8; nj++)
#pragma unroll
            for (int q = 0; q < 4; q++) acc[mi][nj][q] = 0.f;

    load_stage(0, 0);
    asm volatile("cp.async.commit_group;" ::: "memory");
    load_stage(1, 1);
    asm volatile("cp.async.commit_group;" ::: "memory");
    load_stage(2, 2);
    asm volatile("cp.async.commit_group;" ::: "memory");

    const int gsel = lane >> 3;
    const int rin  = lane & 7;
    const int bl   = lane & 15;
    const int bh   = lane >> 4;

    for (int ch = 0; ch < NCH; ch++) {
        if (ch < NCH - 3) asm volatile("cp.async.wait_group 2;" ::: "memory");
        else              asm volatile("cp.async.wait_group 0;" ::: "memory");
        __syncthreads();
        if (ch + 3 < NCH) {
            load_stage(ch + 3, (ch + 3) & 3);
            asm volatile("cp.async.commit_group;" ::: "memory");
        }
        uint32_t sA = sbase + (ch & 3) * 16384;
        uint32_t sB = sA + 8192;
#pragma unroll
        for (int kk = 0; kk < 2; kk++) {
            uint32_t afr[4][4];
#pragma unroll
            for (int mi = 0; mi < 4; mi++) {
                int row   = wm * 64 + mi * 16 + (gsel & 1) * 8 + rin;
                int chunk = kk * 2 + (gsel >> 1);
                uint32_t addr = sA + row * 64 + ((chunk ^ ((row >> 1) & 3)) << 4);
                ldmatrix_x4(afr[mi], addr);
            }
            uint32_t bfr[4][4];
#pragma unroll
            for (int nt = 0; nt < 4; nt++) {
                int krow  = kk * 16 + bl;
                int chunk = wn * 8 + nt * 2 + bh;
                uint32_t addr = sB + krow * 256 + ((chunk ^ (krow & 7)) << 4);
                ldmatrix_x4_trans(bfr[nt], addr);
            }
#pragma unroll
            for (int mi = 0; mi < 4; mi++)
#pragma unroll
                for (int nj = 0; nj < 8; nj++)
                    mma16816(acc[mi][nj], afr[mi],
                             bfr[nj >> 1][(nj & 1) * 2], bfr[nj >> 1][(nj & 1) * 2 + 1]);
        }
    }

    // Epilogue
#pragma unroll
    for (int mi = 0; mi < 4; mi++) {
#pragma unroll
        for (int half = 0; half < 2; half++) {
            int o = o0 + wm * 64 + mi * 16 + half * 8 + (lane >> 2);
            if (mode == 0) {
                int c2 = o / 3;
                int j  = o - c2 * 3;
                float bv = bias[g * 768 + o];
                __half* dst;
                if (j == 0)      dst = g_Q + ((size_t)bg * DIM_ + c2) * S_;
                else if (j == 1) dst = g_K + ((size_t)bg * DIM_ + c2) * SPAD;
                else             dst = g_V + ((size_t)bg * DIM_ + c2) * SPAD;
                dst += t0 + wn * 64 + (lane & 3) * 2;
#pragma unroll
                for (int nj = 0; nj < 8; nj++) {
                    __half2 hv;
                    hv.x = __float2half(acc[mi][nj][half * 2 + 0] + bv);
                    hv.y = __float2half(acc[mi][nj][half * 2 + 1] + bv);
                    *reinterpret_cast<__half2*>(dst + nj * 8) = hv;
                }
            } else {
                float bv = bias[g * 256 + o];
                float* dst = out + ((size_t)bg * 256 + o) * S_
                           + t0 + wn * 64 + (lane & 3) * 2;
#pragma unroll
                for (int nj = 0; nj < 8; nj++) {
                    float2 v;
                    v.x = acc[mi][nj][half * 2 + 0] + bv;
                    v.y = acc[mi][nj][half * 2 + 1] + bv;
                    *reinterpret_cast<float2*>(dst + nj * 8) = v;
                }
            }
        }
    }
}

// ---------------------------------------------------------------------------
// Attention: block (128 s-lanes, 2 g-quads) = 256 threads, 2 CTAs/SM.
// ty owns g in {4ty..4ty+3}: sc[4][16] (64 regs) — kv load+convert amortized
// over 4 g's. K/V staged once per block in smem. Accumulation order over d
// identical to rounds 9/12/13 -> same numerics.
// ---------------------------------------------------------------------------
__global__ __launch_bounds__(256, 2)
void attn_kernel(float* __restrict__ attn_out) {
    __shared__ __half sT[128][136];  // 34 KB tile: rows = e*16+dl, cols = t
    const int tx  = threadIdx.x;     // s lane
    const int ty  = threadIdx.y;     // g quad (0..1)
    const int tid = ty * 128 + tx;
    const int g0  = ty * 4;
    const int s0  = blockIdx.x * 128;
    const int s   = s0 + tx;
    const int n   = blockIdx.y;
    const int b   = blockIdx.z;

    const __half* Kb = g_K + (size_t)b * G_ * DIM_ * SPAD;
    const __half* Vb = g_V + (size_t)b * G_ * DIM_ * SPAD;
    const size_t qbase = ((size_t)b * G_ * DIM_ + g0 * DIM_ + n * 32) * S_ + s;

    float sc[4][16];
#pragma unroll
    for (int gi = 0; gi < 4; gi++)
#pragma unroll
        for (int e = 0; e < 16; e++) sc[gi][e] = 0.f;

    // ---- scores: two d-chunks of 16, K tile staged in smem ----
    for (int hf = 0; hf < 2; hf++) {
        const int d0 = hf * 16;
        __syncthreads();
        for (int j = tid; j < 128 * 17; j += 256) {
            int r = j / 17, c = j - r * 17;
            int e = r >> 4, dl = r & 15;
            const uint4* p = reinterpret_cast<const uint4*>(
                Kb + (size_t)(e * DIM_ + n * 32 + d0 + dl) * SPAD + s0) + c;
            *reinterpret_cast<uint4*>(&sT[r][c * 8]) = *p;
        }
        __syncthreads();
#pragma unroll
        for (int dl = 0; dl < 16; dl++) {
            float qv[4], kv[16];
#pragma unroll
            for (int gi = 0; gi < 4; gi++)
                qv[gi] = __half2float(g_Q[qbase + (size_t)(gi * DIM_ + d0 + dl) * S_]);
#pragma unroll
            for (int e = 0; e < 8; e++) {
                kv[e]     = __half2float(sT[e * 16 + dl][tx]);
                kv[e + 8] = __half2float(sT[e * 16 + dl][tx + 1]);
            }
#pragma unroll
            for (int gi = 0; gi < 4; gi++)
#pragma unroll
                for (int e = 0; e < 16; e++) sc[gi][e] += qv[gi] * kv[e];
        }
    }

    // ---- sigmoid + normalization + attn_out ----
    const float scale = 0.17677669529663687f;  // 1/sqrt(32)
    const size_t abase = (size_t)(b * NH_ + n) * 128 * S_ + s;
#pragma unroll
    for (int gi = 0; gi < 4; gi++) {
        float rs = 1e-9f;
#pragma unroll
        for (int e = 0; e < 16; e++) {
            float z = 1.f / (1.f + __expf(-sc[gi][e] * scale));
            sc[gi][e] = z;
            rs += z;
        }
        float inv = 1.f / rs;
#pragma unroll
        for (int e = 0; e < 16; e++) {
            sc[gi][e] *= inv;
            attn_out[abase + (size_t)((g0 + gi) * 16 + e) * S_] = sc[gi][e];
        }
    }

    // ---- AV: two d-chunks, V tile staged in smem; fp16 into g_Bo ----
    for (int hf = 0; hf < 2; hf++) {
        const int d0 = hf * 16;
        __syncthreads();
        for (int j = tid; j < 128 * 17; j += 256) {
            int r = j / 17, c = j - r * 17;
            int e = r >> 4, dl = r & 15;
            const uint4* p = reinterpret_cast<const uint4*>(
                Vb + (size_t)(e * DIM_ + n * 32 + d0 + dl) * SPAD + s0) + c;
            *reinterpret_cast<uint4*>(&sT[r][c * 8]) = *p;
        }
        __syncthreads();
#pragma unroll
        for (int dl = 0; dl < 16; dl++) {
            float vv[16];
#pragma unroll
            for (int e = 0; e < 8; e++) {
                vv[e]     = __half2float(sT[e * 16 + dl][tx]);
                vv[e + 8] = __half2float(sT[e * 16 + dl][tx + 1]);
            }
#pragma unroll
            for (int gi = 0; gi < 4; gi++) {
                float a = 0.f;
#pragma unroll
                for (int e = 0; e < 16; e++) a += sc[gi][e] * vv[e];
                g_Bo[((size_t)(b * 8 + g0 + gi) * 256 + n * 32 + d0 + dl) * S_ + s] =
                    __float2half(a);
            }
        }
    }
}

// ---------------------------------------------------------------------------
// Serial launcher; attn_kernel is launch #4 for ncu capture.
// ---------------------------------------------------------------------------
extern "C" void kernel_launch(void* const* d_in, const int* in_sizes, int n_in,
                              void* d_out, int out_size) {
    const float* x      = (const float*)d_in[0];
    const float* w_qkv  = (const float*)d_in[1];
    const float* b_qkv  = (const float*)d_in[2];
    const float* w_pred = (const float*)d_in[3];
    const float* b_pred = (const float*)d_in[4];

    float* pred = (float*)d_out;
    float* attn = pred + (size_t)B_ * HID_ * S_;

    void *pAq, *pAp, *pBx, *pBo;
    cudaGetSymbolAddress(&pAq, g_Aq);
    cudaGetSymbolAddress(&pAp, g_Ap);
    cudaGetSymbolAddress(&pBx, g_Bx);
    cudaGetSymbolAddress(&pBo, g_Bo);

    cudaFuncSetAttribute(gemm_mma, cudaFuncAttributeMaxDynamicSharedMemorySize, 65536);

    convert_misc<<<(NWQ + NWP + 32 * 256 + 255) / 256, 256>>>(
        w_qkv, w_pred, b_qkv, (__half*)pAq, (__half*)pAp);

    convert_x<<<32 * 256 * 1024 / 256, 256>>>(x, (__half*)pBx);

    gemm_mma<<<dim3(32, 6, 32), 128, 65536>>>((const __half*)pAq,
                                              (const __half*)pBx,
                                              b_qkv, 768, 0, nullptr);

    attn_kernel<<<dim3(S_ / 128, NH_, B_), dim3(128, 2)>>>(attn);

    gemm_mma<<<dim3(32, 2, 32), 128, 65536>>>((const __half*)pAp,
                                              (const __half*)pBo,
                                              b_pred, 256, 1, pred);
}

// round 15
// speedup vs baseline: 1.4849x; 1.0605x over previous
#include <cuda_runtime.h>
#include <cuda_fp16.h>
#include <cstdint>

// ---------------------------------------------------------------------------
// Problem constants
constexpr int B_   = 4;
constexpr int G_   = 8;
constexpr int NH_  = 8;
constexpr int DIM_ = 256;    // HID / G
constexpr int S_   = 4096;
constexpr int SPAD = 4104;   // padded K/V time pitch (S_+1, rounded to 8)
constexpr int HID_ = 2048;
constexpr int KP   = 256;    // K (plain fp16, single term)

// ---------------------------------------------------------------------------
// Scratch (device globals; allocation is forbidden) — fp16
__device__ __half g_Q[(size_t)B_ * G_ * DIM_ * S_];    // (bg, c, s)
__device__ __half g_K[(size_t)B_ * G_ * DIM_ * SPAD];  // (bg, c, t) t in [0,4096]
__device__ __half g_V[(size_t)B_ * G_ * DIM_ * SPAD];

__device__ __half g_Bx[(size_t)32 * 256 * S_];
__device__ __half g_Bo[(size_t)32 * 256 * S_];
__device__ __half g_Aq[(size_t)G_ * 768 * KP];  // w_qkv fp16 [g][o][c]
__device__ __half g_Ap[(size_t)G_ * 256 * KP];  // w_pred fp16

// ---------------------------------------------------------------------------
__device__ __forceinline__ uint32_t smem_u32(const void* p) {
    uint32_t a;
    asm("{ .reg .u64 t; cvta.to.shared.u64 t, %1; cvt.u32.u64 %0, t; }" : "=r"(a) : "l"(p));
    return a;
}
__device__ __forceinline__ void cp_async16(uint32_t dst, const void* src) {
    asm volatile("cp.async.cg.shared.global [%0], [%1], 16;" :: "r"(dst), "l"(src));
}
__device__ __forceinline__ void ldmatrix_x4(uint32_t* r, uint32_t addr) {
    asm volatile("ldmatrix.sync.aligned.m8n8.x4.shared.b16 {%0,%1,%2,%3}, [%4];"
                 : "=r"(r[0]), "=r"(r[1]), "=r"(r[2]), "=r"(r[3]) : "r"(addr));
}
__device__ __forceinline__ void ldmatrix_x4_trans(uint32_t* r, uint32_t addr) {
    asm volatile("ldmatrix.sync.aligned.m8n8.x4.trans.shared.b16 {%0,%1,%2,%3}, [%4];"
                 : "=r"(r[0]), "=r"(r[1]), "=r"(r[2]), "=r"(r[3]) : "r"(addr));
}
__device__ __forceinline__ void mma16816(float* c, const uint32_t* a, uint32_t b0, uint32_t b1) {
    asm volatile(
        "mma.sync.aligned.m16n8k16.row.col.f32.f16.f16.f32 "
        "{%0,%1,%2,%3}, {%4,%5,%6,%7}, {%8,%9}, {%0,%1,%2,%3};"
        : "+f"(c[0]), "+f"(c[1]), "+f"(c[2]), "+f"(c[3])
        : "r"(a[0]), "r"(a[1]), "r"(a[2]), "r"(a[3]), "r"(b0), "r"(b1));
}

// Packed f32x2 helpers (sm_100+ PTX, plain target OK — not an 'a' feature)
__device__ __forceinline__ unsigned long long pack2(float x, float y) {
    unsigned long long r;
    asm("mov.b64 %0, {%1, %2};" : "=l"(r) : "f"(x), "f"(y));
    return r;
}
__device__ __forceinline__ float2 unpack2(unsigned long long v) {
    float2 r;
    asm("mov.b64 {%0, %1}, %2;" : "=f"(r.x), "=f"(r.y) : "l"(v));
    return r;
}
__device__ __forceinline__ void ffma2(unsigned long long& d, unsigned long long a,
                                      unsigned long long b) {
    asm("fma.rn.f32x2 %0, %1, %2, %0;" : "+l"(d) : "l"(a), "l"(b));
}

// ---------------------------------------------------------------------------
// Fused small conversions: w_qkv -> fp16, w_pred -> fp16, K/V pad fill.
// ---------------------------------------------------------------------------
constexpr int NWQ = G_ * 768 * 256;   // 1572864
constexpr int NWP = G_ * 256 * 256;   // 524288

__global__ void convert_misc(const float* __restrict__ wq,
                             const float* __restrict__ wp,
                             const float* __restrict__ bq,
                             __half* __restrict__ Aq, __half* __restrict__ Ap) {
    int i = blockIdx.x * 256 + threadIdx.x;
    if (i < NWQ) { Aq[i] = __float2half(wq[i]); return; }
    i -= NWQ;
    if (i < NWP) { Ap[i] = __float2half(wp[i]); return; }
    i -= NWP;
    if (i < 32 * 256) {
        int bg = i >> 8, c2 = i & 255, g = bg & 7;
        g_K[((size_t)bg * DIM_ + c2) * SPAD + S_] = __float2half(bq[g * 768 + c2 * 3 + 1]);
        g_V[((size_t)bg * DIM_ + c2) * SPAD + S_] = __float2half(bq[g * 768 + c2 * 3 + 2]);
    }
}

// x fp32 -> g_Bx fp16 (elementwise)
__global__ __launch_bounds__(256)
void convert_x(const float* __restrict__ x, __half* __restrict__ dst) {
    int i = blockIdx.x * 256 + threadIdx.x;  // over 32*256*1024 float4 slots
    size_t base = (size_t)i << 2;
    float4 v = *reinterpret_cast<const float4*>(x + base);
    __half2 h0, h1;
    h0.x = __float2half(v.x); h0.y = __float2half(v.y);
    h1.x = __float2half(v.z); h1.y = __float2half(v.w);
    __half2* dh = reinterpret_cast<__half2*>(dst + base);
    dh[0] = h0; dh[1] = h1;
}

// ---------------------------------------------------------------------------
// mma.sync GEMM: unchanged from round 9 (known good).
// ---------------------------------------------------------------------------
constexpr int NCH = 8;

__global__ __launch_bounds__(128, 2)
void gemm_mma(const __half* __restrict__ Aall,
              const __half* __restrict__ Ball,
              const float* __restrict__ bias,
              int Mtot, int mode, float* __restrict__ out) {
    extern __shared__ __align__(1024) char sbuf[];  // 4 * 16384
    const int tid  = threadIdx.x;
    const int lane = tid & 31;
    const int wid  = tid >> 5;
    const int wm   = wid & 1;
    const int wn   = wid >> 1;
    const int bg = blockIdx.z, g = bg & 7;
    const int o0 = blockIdx.y * 128, t0 = blockIdx.x * 128;

    const uint32_t sbase = smem_u32(sbuf);
    const __half* A  = Aall + ((size_t)g * Mtot + o0) * KP;
    const __half* Bp = Ball + (size_t)bg * 256 * S_;

    auto load_stage = [&](int ch, int st) {
        uint32_t sA = sbase + st * 16384;
        uint32_t sB = sA + 8192;
        const char* a8 = (const char*)A + (size_t)ch * 64;
        const char* b8 = (const char*)(Bp + ((size_t)ch * 32) * S_ + t0);
#pragma unroll
        for (int i = 0; i < 4; i++) {
            int id = tid + i * 128;
            int ra = id >> 2, ca = id & 3;
            uint32_t offA = ra * 64 + ((ca ^ ((ra >> 1) & 3)) << 4);
            cp_async16(sA + offA, a8 + (size_t)ra * (KP * 2) + ca * 16);
            int rb = id >> 4, cb = id & 15;
            uint32_t offB = rb * 256 + ((cb ^ (rb & 7)) << 4);
            cp_async16(sB + offB, b8 + (size_t)rb * (S_ * 2) + cb * 16);
        }
    };

    float acc[4][8][4];
#pragma unroll
    for (int mi = 0; mi < 4; mi++)
#pragma unroll
        for (int nj = 0; nj < 8; nj++)
#pragma unroll
            for (int q = 0; q < 4; q++) acc[mi][nj][q] = 0.f;

    load_stage(0, 0);
    asm volatile("cp.async.commit_group;" ::: "memory");
    load_stage(1, 1);
    asm volatile("cp.async.commit_group;" ::: "memory");
    load_stage(2, 2);
    asm volatile("cp.async.commit_group;" ::: "memory");

    const int gsel = lane >> 3;
    const int rin  = lane & 7;
    const int bl   = lane & 15;
    const int bh   = lane >> 4;

    for (int ch = 0; ch < NCH; ch++) {
        if (ch < NCH - 3) asm volatile("cp.async.wait_group 2;" ::: "memory");
        else              asm volatile("cp.async.wait_group 0;" ::: "memory");
        __syncthreads();
        if (ch + 3 < NCH) {
            load_stage(ch + 3, (ch + 3) & 3);
            asm volatile("cp.async.commit_group;" ::: "memory");
        }
        uint32_t sA = sbase + (ch & 3) * 16384;
        uint32_t sB = sA + 8192;
#pragma unroll
        for (int kk = 0; kk < 2; kk++) {
            uint32_t afr[4][4];
#pragma unroll
            for (int mi = 0; mi < 4; mi++) {
                int row   = wm * 64 + mi * 16 + (gsel & 1) * 8 + rin;
                int chunk = kk * 2 + (gsel >> 1);
                uint32_t addr = sA + row * 64 + ((chunk ^ ((row >> 1) & 3)) << 4);
                ldmatrix_x4(afr[mi], addr);
            }
            uint32_t bfr[4][4];
#pragma unroll
            for (int nt = 0; nt < 4; nt++) {
                int krow  = kk * 16 + bl;
                int chunk = wn * 8 + nt * 2 + bh;
                uint32_t addr = sB + krow * 256 + ((chunk ^ (krow & 7)) << 4);
                ldmatrix_x4_trans(bfr[nt], addr);
            }
#pragma unroll
            for (int mi = 0; mi < 4; mi++)
#pragma unroll
                for (int nj = 0; nj < 8; nj++)
                    mma16816(acc[mi][nj], afr[mi],
                             bfr[nj >> 1][(nj & 1) * 2], bfr[nj >> 1][(nj & 1) * 2 + 1]);
        }
    }

    // Epilogue
#pragma unroll
    for (int mi = 0; mi < 4; mi++) {
#pragma unroll
        for (int half = 0; half < 2; half++) {
            int o = o0 + wm * 64 + mi * 16 + half * 8 + (lane >> 2);
            if (mode == 0) {
                int c2 = o / 3;
                int j  = o - c2 * 3;
                float bv = bias[g * 768 + o];
                __half* dst;
                if (j == 0)      dst = g_Q + ((size_t)bg * DIM_ + c2) * S_;
                else if (j == 1) dst = g_K + ((size_t)bg * DIM_ + c2) * SPAD;
                else             dst = g_V + ((size_t)bg * DIM_ + c2) * SPAD;
                dst += t0 + wn * 64 + (lane & 3) * 2;
#pragma unroll
                for (int nj = 0; nj < 8; nj++) {
                    __half2 hv;
                    hv.x = __float2half(acc[mi][nj][half * 2 + 0] + bv);
                    hv.y = __float2half(acc[mi][nj][half * 2 + 1] + bv);
                    *reinterpret_cast<__half2*>(dst + nj * 8) = hv;
                }
            } else {
                float bv = bias[g * 256 + o];
                float* dst = out + ((size_t)bg * 256 + o) * S_
                           + t0 + wn * 64 + (lane & 3) * 2;
#pragma unroll
                for (int nj = 0; nj < 8; nj++) {
                    float2 v;
                    v.x = acc[mi][nj][half * 2 + 0] + bv;
                    v.y = acc[mi][nj][half * 2 + 1] + bv;
                    *reinterpret_cast<float2*>(dst + nj * 8) = v;
                }
            }
        }
    }
}

// ---------------------------------------------------------------------------
// Attention: block (128 s-lanes, 2 g-quads) = 256 threads, 2 CTAs/SM.
// K/V tile staged in smem as FP32 (converted once at fill). Accumulation via
// packed fma.rn.f32x2 on (e, e+8) pairs = ([tx], [tx+1]) smem neighbors.
// rs summation order kept identical (e = 0..15); AV sum becomes pairwise.
// ---------------------------------------------------------------------------
constexpr int APITCH = 136;                       // floats per tile row
constexpr int ASMEM  = 128 * APITCH * 4;          // 69632 bytes

__global__ __launch_bounds__(256, 2)
void attn_kernel(float* __restrict__ attn_out) {
    extern __shared__ float sF[];    // [128][APITCH] fp32 tile
    const int tx  = threadIdx.x;     // s lane
    const int ty  = threadIdx.y;     // g quad (0..1)
    const int tid = ty * 128 + tx;
    const int g0  = ty * 4;
    const int s0  = blockIdx.x * 128;
    const int s   = s0 + tx;
    const int n   = blockIdx.y;
    const int b   = blockIdx.z;

    const __half* Kb = g_K + (size_t)b * G_ * DIM_ * SPAD;
    const __half* Vb = g_V + (size_t)b * G_ * DIM_ * SPAD;
    const size_t qbase = ((size_t)b * G_ * DIM_ + g0 * DIM_ + n * 32) * S_ + s;

    // packed accumulators: sc2[gi][e] = (score[e], score[e+8])
    unsigned long long sc2[4][8];
#pragma unroll
    for (int gi = 0; gi < 4; gi++)
#pragma unroll
        for (int e = 0; e < 8; e++) sc2[gi][e] = 0ull;

    auto fill_tile = [&](const __half* src, int d0) {
        for (int j = tid; j < 128 * 17; j += 256) {
            int r = j / 17, c = j - r * 17;
            int e = r >> 4, dl = r & 15;
            uint4 v = reinterpret_cast<const uint4*>(
                src + (size_t)(e * DIM_ + n * 32 + d0 + dl) * SPAD + s0)[c];
            const __half2* h = reinterpret_cast<const __half2*>(&v);
            float2 f0 = __half22float2(h[0]);
            float2 f1 = __half22float2(h[1]);
            float2 f2 = __half22float2(h[2]);
            float2 f3 = __half22float2(h[3]);
            float* dst = sF + r * APITCH + c * 8;
            *reinterpret_cast<float4*>(dst)     = make_float4(f0.x, f0.y, f1.x, f1.y);
            *reinterpret_cast<float4*>(dst + 4) = make_float4(f2.x, f2.y, f3.x, f3.y);
        }
    };

    // ---- scores: two d-chunks of 16, K tile in fp32 smem ----
    for (int hf = 0; hf < 2; hf++) {
        const int d0 = hf * 16;
        __syncthreads();
        fill_tile(Kb, d0);
        __syncthreads();
#pragma unroll
        for (int dl = 0; dl < 16; dl++) {
            unsigned long long qv2[4];
#pragma unroll
            for (int gi = 0; gi < 4; gi++) {
                float q = __half2float(g_Q[qbase + (size_t)(gi * DIM_ + d0 + dl) * S_]);
                qv2[gi] = pack2(q, q);
            }
            unsigned long long kv2[8];
#pragma unroll
            for (int e = 0; e < 8; e++) {
                const float* rw = sF + (e * 16 + dl) * APITCH;
                kv2[e] = pack2(rw[tx], rw[tx + 1]);  // (kv[e], kv[e+8])
            }
#pragma unroll
            for (int gi = 0; gi < 4; gi++)
#pragma unroll
                for (int e = 0; e < 8; e++) ffma2(sc2[gi][e], qv2[gi], kv2[e]);
        }
    }

    // ---- sigmoid + normalization + attn_out (rs order = original e 0..15) ----
    const float scale = 0.17677669529663687f;  // 1/sqrt(32)
    const size_t abase = (size_t)(b * NH_ + n) * 128 * S_ + s;
#pragma unroll
    for (int gi = 0; gi < 4; gi++) {
        float z[16];
#pragma unroll
        for (int e = 0; e < 8; e++) {
            float2 p = unpack2(sc2[gi][e]);
            z[e]     = 1.f / (1.f + __expf(-p.x * scale));
            z[e + 8] = 1.f / (1.f + __expf(-p.y * scale));
        }
        float rs = 1e-9f;
#pragma unroll
        for (int e = 0; e < 16; e++) rs += z[e];
        float inv = 1.f / rs;
#pragma unroll
        for (int e = 0; e < 16; e++) {
            z[e] *= inv;
            attn_out[abase + (size_t)((g0 + gi) * 16 + e) * S_] = z[e];
        }
#pragma unroll
        for (int e = 0; e < 8; e++) sc2[gi][e] = pack2(z[e], z[e + 8]);
    }

    // ---- AV: two d-chunks, V tile in fp32 smem; fp16 into g_Bo ----
    for (int hf = 0; hf < 2; hf++) {
        const int d0 = hf * 16;
        __syncthreads();
        fill_tile(Vb, d0);
        __syncthreads();
#pragma unroll
        for (int dl = 0; dl < 16; dl++) {
            unsigned long long vv2[8];
#pragma unroll
            for (int e = 0; e < 8; e++) {
                const float* rw = sF + (e * 16 + dl) * APITCH;
                vv2[e] = pack2(rw[tx], rw[tx + 1]);
            }
#pragma unroll
            for (int gi = 0; gi < 4; gi++) {
                unsigned long long acc2 = 0ull;
#pragma unroll
                for (int e = 0; e < 8; e++) ffma2(acc2, sc2[gi][e], vv2[e]);
                float2 p = unpack2(acc2);
                float a = p.x + p.y;
                g_Bo[((size_t)(b * 8 + g0 + gi) * 256 + n * 32 + d0 + dl) * S_ + s] =
                    __float2half(a);
            }
        }
    }
}

// ---------------------------------------------------------------------------
// Serial launcher; attn_kernel is launch #4 for ncu capture.
// ---------------------------------------------------------------------------
extern "C" void kernel_launch(void* const* d_in, const int* in_sizes, int n_in,
                              void* d_out, int out_size) {
    const float* x      = (const float*)d_in[0];
    const float* w_qkv  = (const float*)d_in[1];
    const float* b_qkv  = (const float*)d_in[2];
    const float* w_pred = (const float*)d_in[3];
    const float* b_pred = (const float*)d_in[4];

    float* pred = (float*)d_out;
    float* attn = pred + (size_t)B_ * HID_ * S_;

    void *pAq, *pAp, *pBx, *pBo;
    cudaGetSymbolAddress(&pAq, g_Aq);
    cudaGetSymbolAddress(&pAp, g_Ap);
    cudaGetSymbolAddress(&pBx, g_Bx);
    cudaGetSymbolAddress(&pBo, g_Bo);

    cudaFuncSetAttribute(gemm_mma, cudaFuncAttributeMaxDynamicSharedMemorySize, 65536);
    cudaFuncSetAttribute(attn_kernel, cudaFuncAttributeMaxDynamicSharedMemorySize, ASMEM);

    convert_misc<<<(NWQ + NWP + 32 * 256 + 255) / 256, 256>>>(
        w_qkv, w_pred, b_qkv, (__half*)pAq, (__half*)pAp);

    convert_x<<<32 * 256 * 1024 / 256, 256>>>(x, (__half*)pBx);

    gemm_mma<<<dim3(32, 6, 32), 128, 65536>>>((const __half*)pAq,
                                              (const __half*)pBx,
                                              b_qkv, 768, 0, nullptr);

    attn_kernel<<<dim3(S_ / 128, NH_, B_), dim3(128, 2), ASMEM>>>(attn);

    gemm_mma<<<dim3(32, 2, 32), 128, 65536>>>((const __half*)pAp,
                                              (const __half*)pBo,
                                              b_pred, 256, 1, pred);
}

// round 16
// speedup vs baseline: 1.5518x; 1.0450x over previous
#include <cuda_runtime.h>
#include <cuda_fp16.h>
#include <cstdint>

// ---------------------------------------------------------------------------
// Problem constants
constexpr int B_   = 4;
constexpr int G_   = 8;
constexpr int NH_  = 8;
constexpr int DIM_ = 256;    // HID / G
constexpr int S_   = 4096;
constexpr int SPAD = 4104;   // padded K/V time pitch (S_+1, rounded to 8)
constexpr int HID_ = 2048;
constexpr int KP   = 256;    // K (plain fp16, single term)

// ---------------------------------------------------------------------------
// Scratch (device globals; allocation is forbidden) — fp16
__device__ __half g_Q[(size_t)B_ * G_ * DIM_ * S_];    // (bg, c, s)
__device__ __half g_K[(size_t)B_ * G_ * DIM_ * SPAD];  // (bg, c, t) t in [0,4096]
__device__ __half g_V[(size_t)B_ * G_ * DIM_ * SPAD];

__device__ __half g_Bx[(size_t)32 * 256 * S_];
__device__ __half g_Bo[(size_t)32 * 256 * S_];
__device__ __half g_Aq[(size_t)G_ * 768 * KP];  // w_qkv fp16 [g][o][c]
__device__ __half g_Ap[(size_t)G_ * 256 * KP];  // w_pred fp16

// ---------------------------------------------------------------------------
__device__ __forceinline__ uint32_t smem_u32(const void* p) {
    uint32_t a;
    asm("{ .reg .u64 t; cvta.to.shared.u64 t, %1; cvt.u32.u64 %0, t; }" : "=r"(a) : "l"(p));
    return a;
}
__device__ __forceinline__ void cp_async16(uint32_t dst, const void* src) {
    asm volatile("cp.async.cg.shared.global [%0], [%1], 16;" :: "r"(dst), "l"(src));
}
__device__ __forceinline__ void ldmatrix_x4(uint32_t* r, uint32_t addr) {
    asm volatile("ldmatrix.sync.aligned.m8n8.x4.shared.b16 {%0,%1,%2,%3}, [%4];"
                 : "=r"(r[0]), "=r"(r[1]), "=r"(r[2]), "=r"(r[3]) : "r"(addr));
}
__device__ __forceinline__ void ldmatrix_x4_trans(uint32_t* r, uint32_t addr) {
    asm volatile("ldmatrix.sync.aligned.m8n8.x4.trans.shared.b16 {%0,%1,%2,%3}, [%4];"
                 : "=r"(r[0]), "=r"(r[1]), "=r"(r[2]), "=r"(r[3]) : "r"(addr));
}
__device__ __forceinline__ void mma16816(float* c, const uint32_t* a, uint32_t b0, uint32_t b1) {
    asm volatile(
        "mma.sync.aligned.m16n8k16.row.col.f32.f16.f16.f32 "
        "{%0,%1,%2,%3}, {%4,%5,%6,%7}, {%8,%9}, {%0,%1,%2,%3};"
        : "+f"(c[0]), "+f"(c[1]), "+f"(c[2]), "+f"(c[3])
        : "r"(a[0]), "r"(a[1]), "r"(a[2]), "r"(a[3]), "r"(b0), "r"(b1));
}

// Packed f32x2 helpers (sm_100+ PTX, plain target OK)
__device__ __forceinline__ unsigned long long pack2(float x, float y) {
    unsigned long long r;
    asm("mov.b64 %0, {%1, %2};" : "=l"(r) : "f"(x), "f"(y));
    return r;
}
__device__ __forceinline__ float2 unpack2(unsigned long long v) {
    float2 r;
    asm("mov.b64 {%0, %1}, %2;" : "=f"(r.x), "=f"(r.y) : "l"(v));
    return r;
}
__device__ __forceinline__ void ffma2(unsigned long long& d, unsigned long long a,
                                      unsigned long long b) {
    asm("fma.rn.f32x2 %0, %1, %2, %0;" : "+l"(d) : "l"(a), "l"(b));
}

// ---------------------------------------------------------------------------
// Fused small conversions: w_qkv -> fp16, w_pred -> fp16, K/V pad fill.
// ---------------------------------------------------------------------------
constexpr int NWQ = G_ * 768 * 256;   // 1572864
constexpr int NWP = G_ * 256 * 256;   // 524288

__global__ void convert_misc(const float* __restrict__ wq,
                             const float* __restrict__ wp,
                             const float* __restrict__ bq,
                             __half* __restrict__ Aq, __half* __restrict__ Ap) {
    int i = blockIdx.x * 256 + threadIdx.x;
    if (i < NWQ) { Aq[i] = __float2half(wq[i]); return; }
    i -= NWQ;
    if (i < NWP) { Ap[i] = __float2half(wp[i]); return; }
    i -= NWP;
    if (i < 32 * 256) {
        int bg = i >> 8, c2 = i & 255, g = bg & 7;
        g_K[((size_t)bg * DIM_ + c2) * SPAD + S_] = __float2half(bq[g * 768 + c2 * 3 + 1]);
        g_V[((size_t)bg * DIM_ + c2) * SPAD + S_] = __float2half(bq[g * 768 + c2 * 3 + 2]);
    }
}

// x fp32 -> g_Bx fp16 (elementwise)
__global__ __launch_bounds__(256)
void convert_x(const float* __restrict__ x, __half* __restrict__ dst) {
    int i = blockIdx.x * 256 + threadIdx.x;  // over 32*256*1024 float4 slots
    size_t base = (size_t)i << 2;
    float4 v = *reinterpret_cast<const float4*>(x + base);
    __half2 h0, h1;
    h0.x = __float2half(v.x); h0.y = __float2half(v.y);
    h1.x = __float2half(v.z); h1.y = __float2half(v.w);
    __half2* dh = reinterpret_cast<__half2*>(dst + base);
    dh[0] = h0; dh[1] = h1;
}

// ---------------------------------------------------------------------------
// mma.sync GEMM: D[128 o x 128 t] = A[o][k 256] . B[t][k 256]
// 4 warps, warp tile 64x64, BK=64 (4 chunks), 3-stage cp.async (32 KB/stage),
// 1 barrier per chunk. K16 feed order identical to the BK=32 version.
// ---------------------------------------------------------------------------
constexpr int NCH       = 4;
constexpr int STAGE_B   = 32768;            // 16 KB A + 16 KB B
constexpr int GSMEM     = 3 * STAGE_B;      // 98304

__global__ __launch_bounds__(128, 2)
void gemm_mma(const __half* __restrict__ Aall,
              const __half* __restrict__ Ball,
              const float* __restrict__ bias,
              int Mtot, int mode, float* __restrict__ out) {
    extern __shared__ __align__(1024) char sbuf[];  // 3 * 32768
    const int tid  = threadIdx.x;
    const int lane = tid & 31;
    const int wid  = tid >> 5;
    const int wm   = wid & 1;
    const int wn   = wid >> 1;
    const int bg = blockIdx.z, g = bg & 7;
    const int o0 = blockIdx.y * 128, t0 = blockIdx.x * 128;

    const uint32_t sbase = smem_u32(sbuf);
    const __half* A  = Aall + ((size_t)g * Mtot + o0) * KP;
    const __half* Bp = Ball + (size_t)bg * 256 * S_;

    // Stage: A 128 rows x 128 B (64 halves), 8 chunks/row, swizzle c^(row&7).
    //        B 64 rows x 256 B, 16 chunks/row, swizzle c^(row&7).
    auto load_stage = [&](int ch, int st) {
        uint32_t sA = sbase + st * STAGE_B;
        uint32_t sB = sA + 16384;
        const char* a8 = (const char*)A + (size_t)ch * 128;                 // ch*64 halves
        const char* b8 = (const char*)(Bp + ((size_t)ch * 64) * S_ + t0);
#pragma unroll
        for (int i = 0; i < 8; i++) {
            int id = tid + i * 128;                 // 0..1023
            int ra = id >> 3, ca = id & 7;          // A: 128 rows x 8 chunks
            uint32_t offA = ra * 128 + ((ca ^ (ra & 7)) << 4);
            cp_async16(sA + offA, a8 + (size_t)ra * (KP * 2) + ca * 16);
            int rb = id >> 4, cb = id & 15;         // B: 64 rows x 16 chunks
            uint32_t offB = rb * 256 + ((cb ^ (rb & 7)) << 4);
            cp_async16(sB + offB, b8 + (size_t)rb * (S_ * 2) + cb * 16);
        }
    };

    float acc[4][8][4];
#pragma unroll
    for (int mi = 0; mi < 4; mi++)
#pragma unroll
        for (int nj = 0; nj < 8; nj++)
#pragma unroll
            for (int q = 0; q < 4; q++) acc[mi][nj][q] = 0.f;

    load_stage(0, 0);
    asm volatile("cp.async.commit_group;" ::: "memory");
    load_stage(1, 1);
    asm volatile("cp.async.commit_group;" ::: "memory");

    const int gsel = lane >> 3;
    const int rin  = lane & 7;
    const int bl   = lane & 15;
    const int bh   = lane >> 4;

    for (int ch = 0; ch < NCH; ch++) {
        if (ch < NCH - 1) asm volatile("cp.async.wait_group 1;" ::: "memory");
        else              asm volatile("cp.async.wait_group 0;" ::: "memory");
        __syncthreads();
        if (ch + 2 < NCH) {
            load_stage(ch + 2, (ch + 2) % 3);
            asm volatile("cp.async.commit_group;" ::: "memory");
        }
        uint32_t sA = sbase + (ch % 3) * STAGE_B;
        uint32_t sB = sA + 16384;
#pragma unroll
        for (int kk = 0; kk < 4; kk++) {
            uint32_t afr[4][4];
#pragma unroll
            for (int mi = 0; mi < 4; mi++) {
                int row   = wm * 64 + mi * 16 + (gsel & 1) * 8 + rin;
                int chunk = kk * 2 + (gsel >> 1);
                uint32_t addr = sA + row * 128 + ((chunk ^ (row & 7)) << 4);
                ldmatrix_x4(afr[mi], addr);
            }
            uint32_t bfr[4][4];
#pragma unroll
            for (int nt = 0; nt < 4; nt++) {
                int krow  = kk * 16 + bl;
                int chunk = wn * 8 + nt * 2 + bh;
                uint32_t addr = sB + krow * 256 + ((chunk ^ (krow & 7)) << 4);
                ldmatrix_x4_trans(bfr[nt], addr);
            }
#pragma unroll
            for (int mi = 0; mi < 4; mi++)
#pragma unroll
                for (int nj = 0; nj < 8; nj++)
                    mma16816(acc[mi][nj], afr[mi],
                             bfr[nj >> 1][(nj & 1) * 2], bfr[nj >> 1][(nj & 1) * 2 + 1]);
        }
    }

    // Epilogue
#pragma unroll
    for (int mi = 0; mi < 4; mi++) {
#pragma unroll
        for (int half = 0; half < 2; half++) {
            int o = o0 + wm * 64 + mi * 16 + half * 8 + (lane >> 2);
            if (mode == 0) {
                int c2 = o / 3;
                int j  = o - c2 * 3;
                float bv = bias[g * 768 + o];
                __half* dst;
                if (j == 0)      dst = g_Q + ((size_t)bg * DIM_ + c2) * S_;
                else if (j == 1) dst = g_K + ((size_t)bg * DIM_ + c2) * SPAD;
                else             dst = g_V + ((size_t)bg * DIM_ + c2) * SPAD;
                dst += t0 + wn * 64 + (lane & 3) * 2;
#pragma unroll
                for (int nj = 0; nj < 8; nj++) {
                    __half2 hv;
                    hv.x = __float2half(acc[mi][nj][half * 2 + 0] + bv);
                    hv.y = __float2half(acc[mi][nj][half * 2 + 1] + bv);
                    *reinterpret_cast<__half2*>(dst + nj * 8) = hv;
                }
            } else {
                float bv = bias[g * 256 + o];
                float* dst = out + ((size_t)bg * 256 + o) * S_
                           + t0 + wn * 64 + (lane & 3) * 2;
#pragma unroll
                for (int nj = 0; nj < 8; nj++) {
                    float2 v;
                    v.x = acc[mi][nj][half * 2 + 0] + bv;
                    v.y = acc[mi][nj][half * 2 + 1] + bv;
                    *reinterpret_cast<float2*>(dst + nj * 8) = v;
                }
            }
        }
    }
}

// ---------------------------------------------------------------------------
// Attention: unchanged from round 15 (fp32 smem tile + fma.rn.f32x2).
// ---------------------------------------------------------------------------
constexpr int APITCH = 136;                       // floats per tile row
constexpr int ASMEM  = 128 * APITCH * 4;          // 69632 bytes

__global__ __launch_bounds__(256, 2)
void attn_kernel(float* __restrict__ attn_out) {
    extern __shared__ float sF[];    // [128][APITCH] fp32 tile
    const int tx  = threadIdx.x;     // s lane
    const int ty  = threadIdx.y;     // g quad (0..1)
    const int tid = ty * 128 + tx;
    const int g0  = ty * 4;
    const int s0  = blockIdx.x * 128;
    const int s   = s0 + tx;
    const int n   = blockIdx.y;
    const int b   = blockIdx.z;

    const __half* Kb = g_K + (size_t)b * G_ * DIM_ * SPAD;
    const __half* Vb = g_V + (size_t)b * G_ * DIM_ * SPAD;
    const size_t qbase = ((size_t)b * G_ * DIM_ + g0 * DIM_ + n * 32) * S_ + s;

    unsigned long long sc2[4][8];
#pragma unroll
    for (int gi = 0; gi < 4; gi++)
#pragma unroll
        for (int e = 0; e < 8; e++) sc2[gi][e] = 0ull;

    auto fill_tile = [&](const __half* src, int d0) {
        for (int j = tid; j < 128 * 17; j += 256) {
            int r = j / 17, c = j - r * 17;
            int e = r >> 4, dl = r & 15;
            uint4 v = reinterpret_cast<const uint4*>(
                src + (size_t)(e * DIM_ + n * 32 + d0 + dl) * SPAD + s0)[c];
            const __half2* h = reinterpret_cast<const __half2*>(&v);
            float2 f0 = __half22float2(h[0]);
            float2 f1 = __half22float2(h[1]);
            float2 f2 = __half22float2(h[2]);
            float2 f3 = __half22float2(h[3]);
            float* dst = sF + r * APITCH + c * 8;
            *reinterpret_cast<float4*>(dst)     = make_float4(f0.x, f0.y, f1.x, f1.y);
            *reinterpret_cast<float4*>(dst + 4) = make_float4(f2.x, f2.y, f3.x, f3.y);
        }
    };

    for (int hf = 0; hf < 2; hf++) {
        const int d0 = hf * 16;
        __syncthreads();
        fill_tile(Kb, d0);
        __syncthreads();
#pragma unroll
        for (int dl = 0; dl < 16; dl++) {
            unsigned long long qv2[4];
#pragma unroll
            for (int gi = 0; gi < 4; gi++) {
                float q = __half2float(g_Q[qbase + (size_t)(gi * DIM_ + d0 + dl) * S_]);
                qv2[gi] = pack2(q, q);
            }
            unsigned long long kv2[8];
#pragma unroll
            for (int e = 0; e < 8; e++) {
                const float* rw = sF + (e * 16 + dl) * APITCH;
                kv2[e] = pack2(rw[tx], rw[tx + 1]);
            }
#pragma unroll
            for (int gi = 0; gi < 4; gi++)
#pragma unroll
                for (int e = 0; e < 8; e++) ffma2(sc2[gi][e], qv2[gi], kv2[e]);
        }
    }

    const float scale = 0.17677669529663687f;  // 1/sqrt(32)
    const size_t abase = (size_t)(b * NH_ + n) * 128 * S_ + s;
#pragma unroll
    for (int gi = 0; gi < 4; gi++) {
        float z[16];
#pragma unroll
        for (int e = 0; e < 8; e++) {
            float2 p = unpack2(sc2[gi][e]);
            z[e]     = 1.f / (1.f + __expf(-p.x * scale));
            z[e + 8] = 1.f / (1.f + __expf(-p.y * scale));
        }
        float rs = 1e-9f;
#pragma unroll
        for (int e = 0; e < 16; e++) rs += z[e];
        float inv = 1.f / rs;
#pragma unroll
        for (int e = 0; e < 16; e++) {
            z[e] *= inv;
            attn_out[abase + (size_t)((g0 + gi) * 16 + e) * S_] = z[e];
        }
#pragma unroll
        for (int e = 0; e < 8; e++) sc2[gi][e] = pack2(z[e], z[e + 8]);
    }

    for (int hf = 0; hf < 2; hf++) {
        const int d0 = hf * 16;
        __syncthreads();
        fill_tile(Vb, d0);
        __syncthreads();
#pragma unroll
        for (int dl = 0; dl < 16; dl++) {
            unsigned long long vv2[8];
#pragma unroll
            for (int e = 0; e < 8; e++) {
                const float* rw = sF + (e * 16 + dl) * APITCH;
                vv2[e] = pack2(rw[tx], rw[tx + 1]);
            }
#pragma unroll
            for (int gi = 0; gi < 4; gi++) {
                unsigned long long acc2 = 0ull;
#pragma unroll
                for (int e = 0; e < 8; e++) ffma2(acc2, sc2[gi][e], vv2[e]);
                float2 p = unpack2(acc2);
                float a = p.x + p.y;
                g_Bo[((size_t)(b * 8 + g0 + gi) * 256 + n * 32 + d0 + dl) * S_ + s] =
                    __float2half(a);
            }
        }
    }
}

// ---------------------------------------------------------------------------
// Serial launcher; attn_kernel is launch #4 for ncu capture.
// ---------------------------------------------------------------------------
extern "C" void kernel_launch(void* const* d_in, const int* in_sizes, int n_in,
                              void* d_out, int out_size) {
    const float* x      = (const float*)d_in[0];
    const float* w_qkv  = (const float*)d_in[1];
    const float* b_qkv  = (const float*)d_in[2];
    const float* w_pred = (const float*)d_in[3];
    const float* b_pred = (const float*)d_in[4];

    float* pred = (float*)d_out;
    float* attn = pred + (size_t)B_ * HID_ * S_;

    void *pAq, *pAp, *pBx, *pBo;
    cudaGetSymbolAddress(&pAq, g_Aq);
    cudaGetSymbolAddress(&pAp, g_Ap);
    cudaGetSymbolAddress(&pBx, g_Bx);
    cudaGetSymbolAddress(&pBo, g_Bo);

    cudaFuncSetAttribute(gemm_mma, cudaFuncAttributeMaxDynamicSharedMemorySize, GSMEM);
    cudaFuncSetAttribute(attn_kernel, cudaFuncAttributeMaxDynamicSharedMemorySize, ASMEM);

    convert_misc<<<(NWQ + NWP + 32 * 256 + 255) / 256, 256>>>(
        w_qkv, w_pred, b_qkv, (__half*)pAq, (__half*)pAp);

    convert_x<<<32 * 256 * 1024 / 256, 256>>>(x, (__half*)pBx);

    gemm_mma<<<dim3(32, 6, 32), 128, GSMEM>>>((const __half*)pAq,
                                              (const __half*)pBx,
                                              b_qkv, 768, 0, nullptr);

    attn_kernel<<<dim3(S_ / 128, NH_, B_), dim3(128, 2), ASMEM>>>(attn);

    gemm_mma<<<dim3(32, 2, 32), 128, GSMEM>>>((const __half*)pAp,
                                              (const __half*)pBo,
                                              b_pred, 256, 1, pred);
}